// round 12
// baseline (speedup 1.0000x reference)
#include <cuda_runtime.h>
#include <cuda_bf16.h>
#include <math.h>

#define B_     64
#define H_     256
#define E_     256
#define V_     64
#define TOTAL_ 2046

// ---------------- static device scratch (alloc-free rule) ----------------
__device__ float g_xg[V_ * 4 * H_];                 // [v][g][h] x@W + bW
__device__ __nv_bfloat16 g_Ubh[512 * 1280];         // U hi, permuted [k][kb*160+g*32+c]
__device__ __nv_bfloat16 g_Ubl[512 * 1280];         // U lo, same layout
__device__ __nv_bfloat16 g_hh[2][B_ * 1024 * H_];   // hidden hi (split bf16)
__device__ __nv_bfloat16 g_hl[2][B_ * 1024 * H_];   // hidden lo
__device__ float g_c[2][B_ * 1024 * H_];            // cell, fp32

__device__ __forceinline__ float sigmoid_(float x) {
    return __fdividef(1.0f, 1.0f + __expf(-x));
}
__device__ __forceinline__ float tanh_(float x) {
    return 1.0f - 2.0f * __fdividef(1.0f, 1.0f + __expf(2.0f * x));
}
__device__ __forceinline__ unsigned s2u_(const void* p) {
    return (unsigned)__cvta_generic_to_shared(p);
}
__device__ __forceinline__ void cpa16_(void* dst, const void* src) {
    asm volatile("cp.async.cg.shared.global [%0], [%1], 16;"
                 :: "r"(s2u_(dst)), "l"(src));
}

#define LDSM_X4(r, addr) \
    asm volatile("ldmatrix.sync.aligned.m8n8.x4.shared.b16 {%0,%1,%2,%3}, [%4];" \
        : "=r"((r)[0]), "=r"((r)[1]), "=r"((r)[2]), "=r"((r)[3]) : "r"(addr))
#define LDSM_X4T(r, addr) \
    asm volatile("ldmatrix.sync.aligned.m8n8.x4.trans.shared.b16 {%0,%1,%2,%3}, [%4];" \
        : "=r"((r)[0]), "=r"((r)[1]), "=r"((r)[2]), "=r"((r)[3]) : "r"(addr))
#define MMA_BF16(d, a, b0, b1) \
    asm volatile("mma.sync.aligned.m16n8k16.row.col.f32.bf16.bf16.f32 " \
        "{%0,%1,%2,%3}, {%4,%5,%6,%7}, {%8,%9}, {%0,%1,%2,%3};" \
        : "+f"((d)[0]), "+f"((d)[1]), "+f"((d)[2]), "+f"((d)[3]) \
        : "r"((a)[0]), "r"((a)[1]), "r"((a)[2]), "r"((a)[3]), "r"(b0), "r"(b1))

// ---------------- prep: xg_table[v][g][h] = emb[v] @ W[g] + bW[g] --------
__global__ void xg_kernel(const float* __restrict__ emb,
                          const float* __restrict__ W,
                          const float* __restrict__ bW) {
    __shared__ float se[E_];
    int v = blockIdx.x;
    int h = threadIdx.x;                     // 256 threads
    se[h] = emb[v * E_ + h];
    __syncthreads();
    float a0 = bW[0 * H_ + h];
    float a1 = bW[1 * H_ + h];
    float a2 = bW[2 * H_ + h];
    float a3 = bW[3 * H_ + h];
    for (int e = 0; e < E_; e++) {
        float x = se[e];
        a0 += x * W[(0 * E_ + e) * H_ + h];
        a1 += x * W[(1 * E_ + e) * H_ + h];
        a2 += x * W[(2 * E_ + e) * H_ + h];
        a3 += x * W[(3 * E_ + e) * H_ + h];
    }
    g_xg[(v * 4 + 0) * H_ + h] = a0;
    g_xg[(v * 4 + 1) * H_ + h] = a1;
    g_xg[(v * 4 + 2) * H_ + h] = a2;
    g_xg[(v * 4 + 3) * H_ + h] = a3;
}

// ---------------- prep: split U into bf16 hi/lo, permuted layout ----------
// g_Ub*[k][kb*160 + g*32 + c] = U[g][k>=256][k&255][kb*32 + c]
__global__ void ucat_split_kernel(const float* __restrict__ U) {
    int idx = blockIdx.x * blockDim.x + threadIdx.x;
    if (idx < 512 * 1280) {
        int k = idx / 1280;
        int np = idx - k * 1280;
        int kb = np / 160;
        int rem = np - kb * 160;
        int g = rem >> 5;
        int c = rem & 31;
        int s = k >> 8;
        int hh = k & 255;
        float v = U[(((g * 2 + s) * H_) + hh) * H_ + kb * 32 + c];
        __nv_bfloat16 hi = __float2bfloat16(v);
        __nv_bfloat16 lo = __float2bfloat16(v - __bfloat162float(hi));
        g_Ubh[idx] = hi;
        g_Ubl[idx] = lo;
    }
}

// ---------------- leaf level (lev 10): children are zero ------------------
__global__ void leaf_kernel(const int* __restrict__ ids) {
    int idx = blockIdx.x * 256 + threadIdx.x;   // 64*1024*256 total
    int r = idx >> 8;
    int k = idx & 255;
    int b = r >> 10;
    int j = r & 1023;
    int id = ids[b * TOTAL_ + 1022 + j];
    const float* xg = &g_xg[id * 4 * H_];
    float ig = sigmoid_(xg[1 * H_ + k]);
    float og = sigmoid_(xg[2 * H_ + k]);
    float ug = tanh_(xg[3 * H_ + k]);
    float cv = ig * ug;
    float hv = og * tanh_(cv);
    __nv_bfloat16 hh = __float2bfloat16(hv);
    g_c[0][idx] = cv;
    g_hh[0][idx] = hh;
    g_hl[0][idx] = __float2bfloat16(hv - __bfloat162float(hh));
}

// ---------------- inner level: tensor-core [hl|hr]@Ucat + fused gates -----
// CTA tile: 128 rows x 32 k-cols (x 5 gates = 160 N). K=512, 16 chunks of 32.
// cp.async 2-stage double buffer; h stored pre-split bf16 hi/lo.
// 512 threads / 16 warps as 8 row-groups x 2 gate-col-halves:
//   warp(wr,wc): rows wr*16..+15, cols {g*32 + wc*16 .. +15 : g=0..4}.
#define BM_ 128
#define TK_ 32
#define APAD_ 40    // A smem row stride (bf16)
#define BPAD_ 168   // B smem row stride (bf16)
#define A_ELEMS_ (BM_ * APAD_)          // 5120 per tile
#define B_ELEMS_ (TK_ * BPAD_)          // 5376 per tile
#define NT_ 512
__global__ __launch_bounds__(NT_) void inner_kernel(
        const int* __restrict__ ids, int off, int log2n,
        int in_buf, int out_buf) {
    extern __shared__ __nv_bfloat16 smem[];
    __nv_bfloat16* Ah = smem;                        // [2][128][APAD_]
    __nv_bfloat16* Al = Ah + 2 * A_ELEMS_;
    __nv_bfloat16* Bh = Al + 2 * A_ELEMS_;           // [2][32][BPAD_]
    __nv_bfloat16* Bl = Bh + 2 * B_ELEMS_;

    const __nv_bfloat16* __restrict__ hhin = g_hh[in_buf];
    const __nv_bfloat16* __restrict__ hlin = g_hl[in_buf];
    const float* __restrict__ cin = g_c[in_buf];
    __nv_bfloat16* __restrict__ hhout = g_hh[out_buf];
    __nv_bfloat16* __restrict__ hlout = g_hl[out_buf];
    float* __restrict__ cout = g_c[out_buf];

    int tid = threadIdx.x;
    int w = tid >> 5;
    int t = tid & 31;
    int wr = w >> 1;                // row group 0..7 (16 rows each)
    int wc = w & 1;                 // gate-col half 0..1
    int rowBase = blockIdx.x * BM_;
    int kb = blockIdx.y;            // H col block: k0 = kb*32

    float acc[5][2][4];             // [gate][n8][frag]
    #pragma unroll
    for (int g = 0; g < 5; g++)
        #pragma unroll
        for (int q = 0; q < 2; q++)
            #pragma unroll
            for (int f = 0; f < 4; f++) acc[g][q][f] = 0.0f;

    int lrow = (t & 7) + ((t >> 3) & 1) * 8;
    int lcol = (t >> 4) * 8;

    auto load_chunk = [&](int kc, int s) {
        int side = kc >> 8;
        int col0 = kc & 255;
        // A: 128 rows x 4 x 16B per tile (hi & lo); 512 slots, 1 per thread
        {
            int row = tid >> 2;
            int q = tid & 3;
            int child = 2 * (rowBase + row) + side;
            long goff = (long)child * H_ + col0 + q * 8;
            cpa16_(&Ah[s * A_ELEMS_ + row * APAD_ + q * 8], hhin + goff);
            cpa16_(&Al[s * A_ELEMS_ + row * APAD_ + q * 8], hlin + goff);
        }
        // B: 32 rows x 20 x 16B per tile (hi & lo); 640 slots
        for (int idx = tid; idx < 640; idx += NT_) {
            int kk = idx / 20;
            int seg = idx - kk * 20;
            long goff = (long)(kc + kk) * 1280 + kb * 160 + seg * 8;
            cpa16_(&Bh[s * B_ELEMS_ + kk * BPAD_ + seg * 8], g_Ubh + goff);
            cpa16_(&Bl[s * B_ELEMS_ + kk * BPAD_ + seg * 8], g_Ubl + goff);
        }
    };

    load_chunk(0, 0);
    asm volatile("cp.async.commit_group;");

    for (int c = 0; c < 16; c++) {
        int s = c & 1;
        if (c + 1 < 16) {
            load_chunk((c + 1) * TK_, (c + 1) & 1);
            asm volatile("cp.async.commit_group;");
            asm volatile("cp.async.wait_group 1;");
        } else {
            asm volatile("cp.async.wait_group 0;");
        }
        __syncthreads();

        #pragma unroll
        for (int ks = 0; ks < 2; ks++) {
            unsigned ah[4], al[4];
            int aro = (wr * 16 + lrow) * APAD_ + ks * 16 + lcol;
            LDSM_X4(ah, s2u_(&Ah[s * A_ELEMS_ + aro]));
            LDSM_X4(al, s2u_(&Al[s * A_ELEMS_ + aro]));
            #pragma unroll
            for (int g = 0; g < 5; g++) {
                unsigned bh[4], bl[4];
                int bso = (ks * 16 + lrow) * BPAD_ + g * 32 + wc * 16 + lcol;
                LDSM_X4T(bh, s2u_(&Bh[s * B_ELEMS_ + bso]));
                LDSM_X4T(bl, s2u_(&Bl[s * B_ELEMS_ + bso]));
                MMA_BF16(acc[g][0], ah, bh[0], bh[1]);
                MMA_BF16(acc[g][0], ah, bl[0], bl[1]);
                MMA_BF16(acc[g][0], al, bh[0], bh[1]);
                MMA_BF16(acc[g][1], ah, bh[2], bh[3]);
                MMA_BF16(acc[g][1], ah, bl[2], bl[3]);
                MMA_BF16(acc[g][1], al, bh[2], bh[3]);
            }
        }
        __syncthreads();
    }

    // ---- epilogue: xg gather + gates + c/h update, h re-split to bf16 ----
    int n = 1 << log2n;
    #pragma unroll
    for (int h2 = 0; h2 < 2; h2++) {
        int r = rowBase + wr * 16 + (t >> 2) + h2 * 8;
        int b = r >> log2n;
        int j = r & (n - 1);
        int id = ids[b * TOTAL_ + off + j];
        const float* xg = &g_xg[id * 4 * H_];
        #pragma unroll
        for (int q = 0; q < 2; q++) {
            int k = kb * 32 + wc * 16 + q * 8 + (t & 3) * 2;
            float2 x0 = *reinterpret_cast<const float2*>(&xg[0 * H_ + k]);
            float2 x1 = *reinterpret_cast<const float2*>(&xg[1 * H_ + k]);
            float2 x2 = *reinterpret_cast<const float2*>(&xg[2 * H_ + k]);
            float2 x3 = *reinterpret_cast<const float2*>(&xg[3 * H_ + k]);
            float2 cl = *reinterpret_cast<const float2*>(&cin[(2 * r) * H_ + k]);
            float2 cr = *reinterpret_cast<const float2*>(&cin[(2 * r + 1) * H_ + k]);
            float2 cv2;
            __nv_bfloat162 hh2, hl2;
            #pragma unroll
            for (int cc = 0; cc < 2; cc++) {
                int i = h2 * 2 + cc;
                float xg0 = cc ? x0.y : x0.x;
                float xg1 = cc ? x1.y : x1.x;
                float xg2 = cc ? x2.y : x2.x;
                float xg3 = cc ? x3.y : x3.x;
                float clv = cc ? cl.y : cl.x;
                float crv = cc ? cr.y : cr.x;
                // gate_map = [0,0,1,2,3]
                float fl = sigmoid_(acc[0][q][i] + xg0);
                float fr = sigmoid_(acc[1][q][i] + xg0);
                float ig = sigmoid_(acc[2][q][i] + xg1);
                float og = sigmoid_(acc[3][q][i] + xg2);
                float ug = tanh_(acc[4][q][i] + xg3);
                float cv = ig * ug + fl * clv + fr * crv;
                float hv = og * tanh_(cv);
                __nv_bfloat16 hh = __float2bfloat16(hv);
                __nv_bfloat16 hl = __float2bfloat16(hv - __bfloat162float(hh));
                if (cc) { cv2.y = cv; hh2.y = hh; hl2.y = hl; }
                else    { cv2.x = cv; hh2.x = hh; hl2.x = hl; }
            }
            *reinterpret_cast<float2*>(&cout[r * H_ + k]) = cv2;
            *reinterpret_cast<__nv_bfloat162*>(&hhout[r * H_ + k]) = hh2;
            *reinterpret_cast<__nv_bfloat162*>(&hlout[r * H_ + k]) = hl2;
        }
    }
}

// ---------------- final: root_hidden + scores -----------------------------
// out layout: [0 .. B*3) scores, [B*3 .. B*3 + B*512) root_hidden
__global__ void final_kernel(const float* __restrict__ Ws,
                             const float* __restrict__ bs,
                             float* __restrict__ out, int buf) {
    __shared__ float red[512];
    int b = blockIdx.x;
    int t = threadIdx.x;                 // 512 threads
    long idx = (long)(b * 2 + (t >> 8)) * H_ + (t & 255);
    float rh = __bfloat162float(g_hh[buf][idx]) + __bfloat162float(g_hl[buf][idx]);
    out[B_ * 3 + b * 512 + t] = rh;
    #pragma unroll
    for (int s = 0; s < 3; s++) {
        red[t] = rh * Ws[t * 3 + s];
        __syncthreads();
        for (int st = 256; st > 0; st >>= 1) {
            if (t < st) red[t] += red[t + st];
            __syncthreads();
        }
        if (t == 0) out[b * 3 + s] = red[0] + bs[s];
        __syncthreads();
    }
}

// ---------------- launcher ------------------------------------------------
extern "C" void kernel_launch(void* const* d_in, const int* in_sizes, int n_in,
                              void* d_out, int out_size) {
    const int*   ids = (const int*)d_in[0];
    const float* emb = (const float*)d_in[1];
    const float* W   = (const float*)d_in[2];
    const float* bW  = (const float*)d_in[3];
    const float* U   = (const float*)d_in[4];
    const float* Ws  = (const float*)d_in[5];
    const float* bs  = (const float*)d_in[6];
    float* out = (float*)d_out;

    int smemBytes = (4 * A_ELEMS_ + 4 * B_ELEMS_) * 2;   // 83968
    static int attrSet = 0;
    if (!attrSet) {
        cudaFuncSetAttribute(inner_kernel,
            cudaFuncAttributeMaxDynamicSharedMemorySize, smemBytes);
        attrSet = 1;
    }

    xg_kernel<<<V_, 256>>>(emb, W, bW);
    ucat_split_kernel<<<(512 * 1280 + 255) / 256, 256>>>(U);
    leaf_kernel<<<(B_ * 1024 * H_) / 256, 256>>>(ids);

    int cur = 0;
    for (int lev = 9; lev >= 1; lev--) {
        int n = 1 << lev;
        int M = B_ * n;
        dim3 grid(M / BM_, 8);
        inner_kernel<<<grid, NT_, smemBytes>>>(ids, n - 2, lev, cur, 1 - cur);
        cur = 1 - cur;
    }
    final_kernel<<<B_, 512>>>(Ws, bs, out, cur);
}

// round 15
// speedup vs baseline: 1.6825x; 1.6825x over previous
#include <cuda_runtime.h>
#include <cuda_fp16.h>
#include <math.h>

#define B_     64
#define H_     256
#define E_     256
#define V_     64
#define TOTAL_ 2046

// ---------------- static device scratch (alloc-free rule) ----------------
__device__ float g_xg[V_ * 4 * H_];            // [v][g][h] x@W + bW
__device__ __half g_Uf[512 * 1280];            // U fp16, permuted [k][kb*160+g*32+c]
__device__ __half g_hh[2][B_ * 1024 * H_];     // hidden hi (fp16 split)
__device__ __half g_hl[2][B_ * 1024 * H_];     // hidden lo
__device__ float g_c[2][B_ * 1024 * H_];       // cell, fp32

__device__ __forceinline__ float sigmoid_(float x) {
    return __fdividef(1.0f, 1.0f + __expf(-x));
}
__device__ __forceinline__ float tanh_(float x) {
    return 1.0f - 2.0f * __fdividef(1.0f, 1.0f + __expf(2.0f * x));
}
__device__ __forceinline__ unsigned s2u_(const void* p) {
    return (unsigned)__cvta_generic_to_shared(p);
}

#define LDSM_X4(r, addr) \
    asm volatile("ldmatrix.sync.aligned.m8n8.x4.shared.b16 {%0,%1,%2,%3}, [%4];" \
        : "=r"((r)[0]), "=r"((r)[1]), "=r"((r)[2]), "=r"((r)[3]) : "r"(addr))
#define LDSM_X4T(r, addr) \
    asm volatile("ldmatrix.sync.aligned.m8n8.x4.trans.shared.b16 {%0,%1,%2,%3}, [%4];" \
        : "=r"((r)[0]), "=r"((r)[1]), "=r"((r)[2]), "=r"((r)[3]) : "r"(addr))
#define MMA_F16(d, a, b0, b1) \
    asm volatile("mma.sync.aligned.m16n8k16.row.col.f32.f16.f16.f32 " \
        "{%0,%1,%2,%3}, {%4,%5,%6,%7}, {%8,%9}, {%0,%1,%2,%3};" \
        : "+f"((d)[0]), "+f"((d)[1]), "+f"((d)[2]), "+f"((d)[3]) \
        : "r"((a)[0]), "r"((a)[1]), "r"((a)[2]), "r"((a)[3]), "r"(b0), "r"(b1))

// ---------------- prep: xg_table[v][g][h] = emb[v] @ W[g] + bW[g] --------
__global__ void xg_kernel(const float* __restrict__ emb,
                          const float* __restrict__ W,
                          const float* __restrict__ bW) {
    __shared__ float se[E_];
    int v = blockIdx.x;
    int h = threadIdx.x;                     // 256 threads
    se[h] = emb[v * E_ + h];
    __syncthreads();
    float a0 = bW[0 * H_ + h];
    float a1 = bW[1 * H_ + h];
    float a2 = bW[2 * H_ + h];
    float a3 = bW[3 * H_ + h];
    for (int e = 0; e < E_; e++) {
        float x = se[e];
        a0 += x * W[(0 * E_ + e) * H_ + h];
        a1 += x * W[(1 * E_ + e) * H_ + h];
        a2 += x * W[(2 * E_ + e) * H_ + h];
        a3 += x * W[(3 * E_ + e) * H_ + h];
    }
    g_xg[(v * 4 + 0) * H_ + h] = a0;
    g_xg[(v * 4 + 1) * H_ + h] = a1;
    g_xg[(v * 4 + 2) * H_ + h] = a2;
    g_xg[(v * 4 + 3) * H_ + h] = a3;
}

// ---------------- prep: U -> fp16, permuted layout ------------------------
// g_Uf[k][kb*160 + g*32 + c] = U[g][k>=256][k&255][kb*32 + c]
__global__ void ucat_kernel(const float* __restrict__ U) {
    int idx = blockIdx.x * blockDim.x + threadIdx.x;
    if (idx < 512 * 1280) {
        int k = idx / 1280;
        int np = idx - k * 1280;
        int kb = np / 160;
        int rem = np - kb * 160;
        int g = rem >> 5;
        int c = rem & 31;
        int s = k >> 8;
        int hh = k & 255;
        g_Uf[idx] = __float2half(U[(((g * 2 + s) * H_) + hh) * H_ + kb * 32 + c]);
    }
}

// ---------------- leaf level (lev 10): children are zero ------------------
__global__ void leaf_kernel(const int* __restrict__ ids) {
    int idx = blockIdx.x * 256 + threadIdx.x;   // 64*1024*256 total
    int r = idx >> 8;
    int k = idx & 255;
    int b = r >> 10;
    int j = r & 1023;
    int id = ids[b * TOTAL_ + 1022 + j];
    const float* xg = &g_xg[id * 4 * H_];
    float ig = sigmoid_(xg[1 * H_ + k]);
    float og = sigmoid_(xg[2 * H_ + k]);
    float ug = tanh_(xg[3 * H_ + k]);
    float cv = ig * ug;
    float hv = og * tanh_(cv);
    __half hh = __float2half(hv);
    g_c[0][idx] = cv;
    g_hh[0][idx] = hh;
    g_hl[0][idx] = __float2half(hv - __half2float(hh));
}

// ---------------- inner level: tensor-core [hl|hr]@Ucat + fused gates -----
// CTA tile: 128 rows x 32 k-cols (x 5 gates = 160 N). K=512 in 32-chunks.
// fp16: A (child h) split hi+lo (2 products), B (U) single fp16.
// 8 warps; warp w handles rows w*16..w*16+15, all 160 N cols.
#define BM_ 128
#define TK_ 32
#define APAD_ 40    // A smem row stride (fp16)
#define BPAD_ 168   // B smem row stride (fp16)
__global__ __launch_bounds__(256, 2) void inner_kernel(
        const int* __restrict__ ids, int off, int log2n,
        int in_buf, int out_buf) {
    __shared__ __align__(16) __half Ah[BM_][APAD_];
    __shared__ __align__(16) __half Al[BM_][APAD_];
    __shared__ __align__(16) __half Bs[TK_][BPAD_];

    const __half* __restrict__ hhin = g_hh[in_buf];
    const __half* __restrict__ hlin = g_hl[in_buf];
    const float* __restrict__ cin = g_c[in_buf];
    __half* __restrict__ hhout = g_hh[out_buf];
    __half* __restrict__ hlout = g_hl[out_buf];
    float* __restrict__ cout = g_c[out_buf];

    int tid = threadIdx.x;
    int w = tid >> 5;
    int t = tid & 31;
    int rowBase = blockIdx.x * BM_;
    int kb = blockIdx.y;            // H col block: k0 = kb*32
    int k0 = kb * 32;

    float acc[20][4];               // [n8-tile][frag]; nt = g*4 + q
    #pragma unroll
    for (int i = 0; i < 20; i++)
        #pragma unroll
        for (int j = 0; j < 4; j++) acc[i][j] = 0.0f;

    int lrow = (t & 7) + ((t >> 3) & 1) * 8;   // row within 16
    int lcol = (t >> 4) * 8;                   // col-half within 16

    for (int kc = 0; kc < 512; kc += TK_) {
        // ---- A tile: 128 rows x 32 k fp16 hi & lo (pure 16B copies) ----
        int side = kc >> 8;                    // left / right child
        int col0 = kc & 255;                   // col base within child row
        #pragma unroll
        for (int it = 0; it < 2; it++) {
            int idx = tid + it * 256;          // 0..511 chunk slots
            int row = idx >> 2;
            int q = idx & 3;                   // 4 x 8-half chunks per row
            int child = 2 * (rowBase + row) + side;
            long gs = (long)child * H_ + col0 + q * 8;
            *reinterpret_cast<uint4*>(&Ah[row][q * 8]) =
                *reinterpret_cast<const uint4*>(hhin + gs);
            *reinterpret_cast<uint4*>(&Al[row][q * 8]) =
                *reinterpret_cast<const uint4*>(hlin + gs);
        }
        // ---- B tile: 32 k-rows x 160 cols fp16 ----
        for (int idx = tid; idx < 640; idx += 256) {
            int kk = idx / 20;
            int seg = idx - kk * 20;
            long gs = (long)(kc + kk) * 1280 + kb * 160 + seg * 8;
            *reinterpret_cast<uint4*>(&Bs[kk][seg * 8]) =
                *reinterpret_cast<const uint4*>(g_Uf + gs);
        }
        __syncthreads();

        #pragma unroll
        for (int ks = 0; ks < 2; ks++) {
            unsigned ah[4], al[4];
            int acol = ks * 16 + lcol;
            LDSM_X4(ah, s2u_(&Ah[w * 16 + lrow][acol]));
            LDSM_X4(al, s2u_(&Al[w * 16 + lrow][acol]));
            #pragma unroll
            for (int ntp = 0; ntp < 10; ntp++) {
                unsigned bf[4];
                LDSM_X4T(bf, s2u_(&Bs[ks * 16 + lrow][ntp * 16 + lcol]));
                // n8-tile 2*ntp  (b frags 0,1): Ah*B + Al*B
                MMA_F16(acc[2 * ntp], ah, bf[0], bf[1]);
                MMA_F16(acc[2 * ntp], al, bf[0], bf[1]);
                // n8-tile 2*ntp+1 (b frags 2,3)
                MMA_F16(acc[2 * ntp + 1], ah, bf[2], bf[3]);
                MMA_F16(acc[2 * ntp + 1], al, bf[2], bf[3]);
            }
        }
        __syncthreads();
    }

    // ---- epilogue: xg gather + gates + c/h update, h split to fp16 ----
    // C frag: thread t holds rows w*16 + t/4 (+8), cols (t%4)*2 (+1) of each
    // n8-tile; gates are 4 n8-tiles apart -> all 5 gates local per (row,col).
    int n = 1 << log2n;
    #pragma unroll
    for (int h2 = 0; h2 < 2; h2++) {
        int r = rowBase + w * 16 + (t >> 2) + h2 * 8;
        int b = r >> log2n;
        int j = r & (n - 1);
        int id = ids[b * TOTAL_ + off + j];
        const float* xg = &g_xg[id * 4 * H_];
        #pragma unroll
        for (int q = 0; q < 4; q++) {
            int k = k0 + q * 8 + (t & 3) * 2;
            float2 x0 = *reinterpret_cast<const float2*>(&xg[0 * H_ + k]);
            float2 x1 = *reinterpret_cast<const float2*>(&xg[1 * H_ + k]);
            float2 x2 = *reinterpret_cast<const float2*>(&xg[2 * H_ + k]);
            float2 x3 = *reinterpret_cast<const float2*>(&xg[3 * H_ + k]);
            float2 cl = *reinterpret_cast<const float2*>(&cin[(2 * r) * H_ + k]);
            float2 cr = *reinterpret_cast<const float2*>(&cin[(2 * r + 1) * H_ + k]);
            float2 cv2;
            __half2 hh2, hl2;
            #pragma unroll
            for (int cc = 0; cc < 2; cc++) {
                int i = h2 * 2 + cc;
                float xg0 = cc ? x0.y : x0.x;
                float xg1 = cc ? x1.y : x1.x;
                float xg2 = cc ? x2.y : x2.x;
                float xg3 = cc ? x3.y : x3.x;
                float clv = cc ? cl.y : cl.x;
                float crv = cc ? cr.y : cr.x;
                // gate_map = [0,0,1,2,3]
                float fl = sigmoid_(acc[0 * 4 + q][i] + xg0);
                float fr = sigmoid_(acc[1 * 4 + q][i] + xg0);
                float ig = sigmoid_(acc[2 * 4 + q][i] + xg1);
                float og = sigmoid_(acc[3 * 4 + q][i] + xg2);
                float ug = tanh_(acc[4 * 4 + q][i] + xg3);
                float cv = ig * ug + fl * clv + fr * crv;
                float hv = og * tanh_(cv);
                __half hh = __float2half(hv);
                __half hl = __float2half(hv - __half2float(hh));
                if (cc) { cv2.y = cv; hh2.y = hh; hl2.y = hl; }
                else    { cv2.x = cv; hh2.x = hh; hl2.x = hl; }
            }
            *reinterpret_cast<float2*>(&cout[r * H_ + k]) = cv2;
            *reinterpret_cast<__half2*>(&hhout[r * H_ + k]) = hh2;
            *reinterpret_cast<__half2*>(&hlout[r * H_ + k]) = hl2;
        }
    }
}

// ---------------- final: root_hidden + scores -----------------------------
// out layout: [0 .. B*3) scores, [B*3 .. B*3 + B*512) root_hidden
__global__ void final_kernel(const float* __restrict__ Ws,
                             const float* __restrict__ bs,
                             float* __restrict__ out, int buf) {
    __shared__ float red[512];
    int b = blockIdx.x;
    int t = threadIdx.x;                 // 512 threads
    long idx = (long)(b * 2 + (t >> 8)) * H_ + (t & 255);
    float rh = __half2float(g_hh[buf][idx]) + __half2float(g_hl[buf][idx]);
    out[B_ * 3 + b * 512 + t] = rh;
    #pragma unroll
    for (int s = 0; s < 3; s++) {
        red[t] = rh * Ws[t * 3 + s];
        __syncthreads();
        for (int st = 256; st > 0; st >>= 1) {
            if (t < st) red[t] += red[t + st];
            __syncthreads();
        }
        if (t == 0) out[b * 3 + s] = red[0] + bs[s];
        __syncthreads();
    }
}

// ---------------- launcher ------------------------------------------------
extern "C" void kernel_launch(void* const* d_in, const int* in_sizes, int n_in,
                              void* d_out, int out_size) {
    const int*   ids = (const int*)d_in[0];
    const float* emb = (const float*)d_in[1];
    const float* W   = (const float*)d_in[2];
    const float* bW  = (const float*)d_in[3];
    const float* U   = (const float*)d_in[4];
    const float* Ws  = (const float*)d_in[5];
    const float* bs  = (const float*)d_in[6];
    float* out = (float*)d_out;

    xg_kernel<<<V_, 256>>>(emb, W, bW);
    ucat_kernel<<<(512 * 1280 + 255) / 256, 256>>>(U);
    leaf_kernel<<<(B_ * 1024 * H_) / 256, 256>>>(ids);

    int cur = 0;
    for (int lev = 9; lev >= 1; lev--) {
        int n = 1 << lev;
        int M = B_ * n;
        dim3 grid(M / BM_, 8);
        inner_kernel<<<grid, 256>>>(ids, n - 2, lev, cur, 1 - cur);
        cur = 1 - cur;
    }
    final_kernel<<<B_, 512>>>(Ws, bs, out, cur);
}

// round 16
// speedup vs baseline: 2.2489x; 1.3367x over previous
#include <cuda_runtime.h>
#include <cuda_fp16.h>
#include <math.h>

#define B_     64
#define H_     256
#define E_     256
#define V_     64
#define TOTAL_ 2046

// ---------------- static device scratch (alloc-free rule) ----------------
__device__ float g_xg[V_ * 4 * H_];            // [v][g][h] x@W + bW
__device__ __half g_Uf[512 * 1280];            // U fp16, permuted [k][kb*160+g*32+c]
__device__ __half g_hh[2][B_ * 1024 * H_];     // hidden hi (fp16 split)
__device__ __half g_hl[2][B_ * 1024 * H_];     // hidden lo
__device__ float g_c[2][B_ * 1024 * H_];       // cell, fp32

__device__ __forceinline__ float sigmoid_(float x) {
    return __fdividef(1.0f, 1.0f + __expf(-x));
}
__device__ __forceinline__ float tanh_(float x) {
    return 1.0f - 2.0f * __fdividef(1.0f, 1.0f + __expf(2.0f * x));
}
__device__ __forceinline__ unsigned s2u_(const void* p) {
    return (unsigned)__cvta_generic_to_shared(p);
}
__device__ __forceinline__ void cpa16_(unsigned dst, const void* src) {
    asm volatile("cp.async.cg.shared.global [%0], [%1], 16;"
                 :: "r"(dst), "l"(src));
}

#define LDSM_X4(r, addr) \
    asm volatile("ldmatrix.sync.aligned.m8n8.x4.shared.b16 {%0,%1,%2,%3}, [%4];" \
        : "=r"((r)[0]), "=r"((r)[1]), "=r"((r)[2]), "=r"((r)[3]) : "r"(addr))
#define LDSM_X4T(r, addr) \
    asm volatile("ldmatrix.sync.aligned.m8n8.x4.trans.shared.b16 {%0,%1,%2,%3}, [%4];" \
        : "=r"((r)[0]), "=r"((r)[1]), "=r"((r)[2]), "=r"((r)[3]) : "r"(addr))
#define MMA_F16(d, a, b0, b1) \
    asm volatile("mma.sync.aligned.m16n8k16.row.col.f32.f16.f16.f32 " \
        "{%0,%1,%2,%3}, {%4,%5,%6,%7}, {%8,%9}, {%0,%1,%2,%3};" \
        : "+f"((d)[0]), "+f"((d)[1]), "+f"((d)[2]), "+f"((d)[3]) \
        : "r"((a)[0]), "r"((a)[1]), "r"((a)[2]), "r"((a)[3]), "r"(b0), "r"(b1))

// ---------------- prep: xg_table[v][g][h] = emb[v] @ W[g] + bW[g] --------
__global__ void xg_kernel(const float* __restrict__ emb,
                          const float* __restrict__ W,
                          const float* __restrict__ bW) {
    __shared__ float se[E_];
    int v = blockIdx.x;
    int h = threadIdx.x;                     // 256 threads
    se[h] = emb[v * E_ + h];
    __syncthreads();
    float a0 = bW[0 * H_ + h];
    float a1 = bW[1 * H_ + h];
    float a2 = bW[2 * H_ + h];
    float a3 = bW[3 * H_ + h];
    for (int e = 0; e < E_; e++) {
        float x = se[e];
        a0 += x * W[(0 * E_ + e) * H_ + h];
        a1 += x * W[(1 * E_ + e) * H_ + h];
        a2 += x * W[(2 * E_ + e) * H_ + h];
        a3 += x * W[(3 * E_ + e) * H_ + h];
    }
    g_xg[(v * 4 + 0) * H_ + h] = a0;
    g_xg[(v * 4 + 1) * H_ + h] = a1;
    g_xg[(v * 4 + 2) * H_ + h] = a2;
    g_xg[(v * 4 + 3) * H_ + h] = a3;
}

// ---------------- prep: U -> fp16, permuted layout ------------------------
// g_Uf[k][kb*160 + g*32 + c] = U[g][k>=256][k&255][kb*32 + c]
__global__ void ucat_kernel(const float* __restrict__ U) {
    int idx = blockIdx.x * blockDim.x + threadIdx.x;
    if (idx < 512 * 1280) {
        int k = idx / 1280;
        int np = idx - k * 1280;
        int kb = np / 160;
        int rem = np - kb * 160;
        int g = rem >> 5;
        int c = rem & 31;
        int s = k >> 8;
        int hh = k & 255;
        g_Uf[idx] = __float2half(U[(((g * 2 + s) * H_) + hh) * H_ + kb * 32 + c]);
    }
}

// ---------------- leaf level (lev 10): children are zero ------------------
__global__ void leaf_kernel(const int* __restrict__ ids) {
    int idx = blockIdx.x * 256 + threadIdx.x;   // 64*1024*256 total
    int r = idx >> 8;
    int k = idx & 255;
    int b = r >> 10;
    int j = r & 1023;
    int id = ids[b * TOTAL_ + 1022 + j];
    const float* xg = &g_xg[id * 4 * H_];
    float ig = sigmoid_(xg[1 * H_ + k]);
    float og = sigmoid_(xg[2 * H_ + k]);
    float ug = tanh_(xg[3 * H_ + k]);
    float cv = ig * ug;
    float hv = og * tanh_(cv);
    __half hh = __float2half(hv);
    g_c[0][idx] = cv;
    g_hh[0][idx] = hh;
    g_hl[0][idx] = __float2half(hv - __half2float(hh));
}

// ---------------- inner level: tensor-core [hl|hr]@Ucat + fused gates -----
// CTA tile: 128 rows x 32 k-cols (x 5 gates = 160 N). K=512 in 32-chunks.
// fp16: A (child h) split hi+lo (2 products), B (U) single fp16.
// 2-stage cp.async double-buffered pipeline hides L2 latency.
// 8 warps; warp w handles rows w*16..w*16+15, all 160 N cols.
#define BM_ 128
#define TK_ 32
#define APAD_ 40    // A smem row stride (fp16)
#define BPAD_ 168   // B smem row stride (fp16)
#define A_EL_ (BM_ * APAD_)     // 5120 halves per stage
#define B_EL_ (TK_ * BPAD_)     // 5376 halves per stage
__global__ __launch_bounds__(256, 2) void inner_kernel(
        const int* __restrict__ ids, int off, int log2n,
        int in_buf, int out_buf) {
    extern __shared__ __align__(16) __half sm[];
    __half* AhS = sm;                     // [2][BM_][APAD_]
    __half* AlS = sm + 2 * A_EL_;         // [2][BM_][APAD_]
    __half* BsS = sm + 4 * A_EL_;         // [2][TK_][BPAD_]

    const __half* __restrict__ hhin = g_hh[in_buf];
    const __half* __restrict__ hlin = g_hl[in_buf];
    const float* __restrict__ cin = g_c[in_buf];
    __half* __restrict__ hhout = g_hh[out_buf];
    __half* __restrict__ hlout = g_hl[out_buf];
    float* __restrict__ cout = g_c[out_buf];

    int tid = threadIdx.x;
    int w = tid >> 5;
    int t = tid & 31;
    int rowBase = blockIdx.x * BM_;
    int kb = blockIdx.y;            // H col block: k0 = kb*32
    int k0 = kb * 32;

    float acc[20][4];               // [n8-tile][frag]; nt = g*4 + q
    #pragma unroll
    for (int i = 0; i < 20; i++)
        #pragma unroll
        for (int j = 0; j < 4; j++) acc[i][j] = 0.0f;

    int lrow = (t & 7) + ((t >> 3) & 1) * 8;   // row within 16
    int lcol = (t >> 4) * 8;                   // col-half within 16

    auto load_chunk = [&](int kc, int s) {
        int side = kc >> 8;                    // left / right child
        int col0 = kc & 255;                   // col base within child row
        unsigned ah = s2u_(AhS + s * A_EL_);
        unsigned al = s2u_(AlS + s * A_EL_);
        unsigned bb = s2u_(BsS + s * B_EL_);
        // A: 512 16B-slots each for hi & lo
        #pragma unroll
        for (int it = 0; it < 2; it++) {
            int idx = tid + it * 256;          // 0..511
            int row = idx >> 2;
            int q = idx & 3;
            int child = 2 * (rowBase + row) + side;
            long gs = (long)child * H_ + col0 + q * 8;
            unsigned d = (unsigned)(row * APAD_ + q * 8) * 2;
            cpa16_(ah + d, hhin + gs);
            cpa16_(al + d, hlin + gs);
        }
        // B: 640 16B-slots
        for (int idx = tid; idx < 640; idx += 256) {
            int kk = idx / 20;
            int seg = idx - kk * 20;
            long gs = (long)(kc + kk) * 1280 + kb * 160 + seg * 8;
            cpa16_(bb + (unsigned)(kk * BPAD_ + seg * 8) * 2, g_Uf + gs);
        }
    };

    load_chunk(0, 0);
    asm volatile("cp.async.commit_group;");

    for (int c = 0; c < 16; c++) {
        int s = c & 1;
        if (c + 1 < 16) {
            load_chunk((c + 1) * TK_, 1 - s);
            asm volatile("cp.async.commit_group;");
            asm volatile("cp.async.wait_group 1;");
        } else {
            asm volatile("cp.async.wait_group 0;");
        }
        __syncthreads();

        const __half* Ahp = AhS + s * A_EL_;
        const __half* Alp = AlS + s * A_EL_;
        const __half* Bsp = BsS + s * B_EL_;
        #pragma unroll
        for (int ks = 0; ks < 2; ks++) {
            unsigned ah[4], al[4];
            int aro = (w * 16 + lrow) * APAD_ + ks * 16 + lcol;
            LDSM_X4(ah, s2u_(Ahp + aro));
            LDSM_X4(al, s2u_(Alp + aro));
            #pragma unroll
            for (int ntp = 0; ntp < 10; ntp++) {
                unsigned bf[4];
                LDSM_X4T(bf, s2u_(Bsp + (ks * 16 + lrow) * BPAD_ + ntp * 16 + lcol));
                MMA_F16(acc[2 * ntp], ah, bf[0], bf[1]);
                MMA_F16(acc[2 * ntp], al, bf[0], bf[1]);
                MMA_F16(acc[2 * ntp + 1], ah, bf[2], bf[3]);
                MMA_F16(acc[2 * ntp + 1], al, bf[2], bf[3]);
            }
        }
        __syncthreads();
    }

    // ---- epilogue: xg gather + gates + c/h update, h split to fp16 ----
    // C frag: thread t holds rows w*16 + t/4 (+8), cols (t%4)*2 (+1) of each
    // n8-tile; gates are 4 n8-tiles apart -> all 5 gates local per (row,col).
    int n = 1 << log2n;
    #pragma unroll
    for (int h2 = 0; h2 < 2; h2++) {
        int r = rowBase + w * 16 + (t >> 2) + h2 * 8;
        int b = r >> log2n;
        int j = r & (n - 1);
        int id = ids[b * TOTAL_ + off + j];
        const float* xg = &g_xg[id * 4 * H_];
        #pragma unroll
        for (int q = 0; q < 4; q++) {
            int k = k0 + q * 8 + (t & 3) * 2;
            float2 x0 = *reinterpret_cast<const float2*>(&xg[0 * H_ + k]);
            float2 x1 = *reinterpret_cast<const float2*>(&xg[1 * H_ + k]);
            float2 x2 = *reinterpret_cast<const float2*>(&xg[2 * H_ + k]);
            float2 x3 = *reinterpret_cast<const float2*>(&xg[3 * H_ + k]);
            float2 cl = *reinterpret_cast<const float2*>(&cin[(2 * r) * H_ + k]);
            float2 cr = *reinterpret_cast<const float2*>(&cin[(2 * r + 1) * H_ + k]);
            float2 cv2;
            __half2 hh2, hl2;
            #pragma unroll
            for (int cc = 0; cc < 2; cc++) {
                int i = h2 * 2 + cc;
                float xg0 = cc ? x0.y : x0.x;
                float xg1 = cc ? x1.y : x1.x;
                float xg2 = cc ? x2.y : x2.x;
                float xg3 = cc ? x3.y : x3.x;
                float clv = cc ? cl.y : cl.x;
                float crv = cc ? cr.y : cr.x;
                // gate_map = [0,0,1,2,3]
                float fl = sigmoid_(acc[0 * 4 + q][i] + xg0);
                float fr = sigmoid_(acc[1 * 4 + q][i] + xg0);
                float ig = sigmoid_(acc[2 * 4 + q][i] + xg1);
                float og = sigmoid_(acc[3 * 4 + q][i] + xg2);
                float ug = tanh_(acc[4 * 4 + q][i] + xg3);
                float cv = ig * ug + fl * clv + fr * crv;
                float hv = og * tanh_(cv);
                __half hh = __float2half(hv);
                __half hl = __float2half(hv - __half2float(hh));
                if (cc) { cv2.y = cv; hh2.y = hh; hl2.y = hl; }
                else    { cv2.x = cv; hh2.x = hh; hl2.x = hl; }
            }
            *reinterpret_cast<float2*>(&cout[r * H_ + k]) = cv2;
            *reinterpret_cast<__half2*>(&hhout[r * H_ + k]) = hh2;
            *reinterpret_cast<__half2*>(&hlout[r * H_ + k]) = hl2;
        }
    }
}

// ---------------- final: root_hidden + scores -----------------------------
// out layout: [0 .. B*3) scores, [B*3 .. B*3 + B*512) root_hidden
__global__ void final_kernel(const float* __restrict__ Ws,
                             const float* __restrict__ bs,
                             float* __restrict__ out, int buf) {
    __shared__ float red[512];
    int b = blockIdx.x;
    int t = threadIdx.x;                 // 512 threads
    long idx = (long)(b * 2 + (t >> 8)) * H_ + (t & 255);
    float rh = __half2float(g_hh[buf][idx]) + __half2float(g_hl[buf][idx]);
    out[B_ * 3 + b * 512 + t] = rh;
    #pragma unroll
    for (int s = 0; s < 3; s++) {
        red[t] = rh * Ws[t * 3 + s];
        __syncthreads();
        for (int st = 256; st > 0; st >>= 1) {
            if (t < st) red[t] += red[t + st];
            __syncthreads();
        }
        if (t == 0) out[b * 3 + s] = red[0] + bs[s];
        __syncthreads();
    }
}

// ---------------- launcher ------------------------------------------------
extern "C" void kernel_launch(void* const* d_in, const int* in_sizes, int n_in,
                              void* d_out, int out_size) {
    const int*   ids = (const int*)d_in[0];
    const float* emb = (const float*)d_in[1];
    const float* W   = (const float*)d_in[2];
    const float* bW  = (const float*)d_in[3];
    const float* U   = (const float*)d_in[4];
    const float* Ws  = (const float*)d_in[5];
    const float* bs  = (const float*)d_in[6];
    float* out = (float*)d_out;

    int smemBytes = (4 * A_EL_ + 2 * B_EL_) * 2;   // 62464 B
    static int attrSet = 0;
    if (!attrSet) {
        cudaFuncSetAttribute(inner_kernel,
            cudaFuncAttributeMaxDynamicSharedMemorySize, smemBytes);
        attrSet = 1;
    }

    xg_kernel<<<V_, 256>>>(emb, W, bW);
    ucat_kernel<<<(512 * 1280 + 255) / 256, 256>>>(U);
    leaf_kernel<<<(B_ * 1024 * H_) / 256, 256>>>(ids);

    int cur = 0;
    for (int lev = 9; lev >= 1; lev--) {
        int n = 1 << lev;
        int M = B_ * n;
        dim3 grid(M / BM_, 8);
        inner_kernel<<<grid, 256, smemBytes>>>(ids, n - 2, lev, cur, 1 - cur);
        cur = 1 - cur;
    }
    final_kernel<<<B_, 512>>>(Ws, bs, out, cur);
}

// round 17
// speedup vs baseline: 3.2382x; 1.4399x over previous
#include <cuda_runtime.h>
#include <cuda_fp16.h>
#include <math.h>

#define B_     64
#define H_     256
#define E_     256
#define V_     64
#define TOTAL_ 2046

// ---------------- static device scratch (alloc-free rule) ----------------
__device__ float g_xg[V_ * 4 * H_];            // [v][g][h] x@W + bW
__device__ __half g_Uf[512 * 1280];            // U fp16, permuted [k][kb*160+g*32+c]
__device__ __half g_hh[2][B_ * 1024 * H_];     // hidden, fp16
__device__ float g_c[2][B_ * 1024 * H_];       // cell, fp32
__device__ float g_hf[B_ * 2 * H_];            // root-level hidden, fp32 (output)

__device__ __forceinline__ float sigmoid_(float x) {
    return __fdividef(1.0f, 1.0f + __expf(-x));
}
__device__ __forceinline__ float tanh_(float x) {
    return 1.0f - 2.0f * __fdividef(1.0f, 1.0f + __expf(2.0f * x));
}
__device__ __forceinline__ unsigned s2u_(const void* p) {
    return (unsigned)__cvta_generic_to_shared(p);
}
__device__ __forceinline__ void cpa16_(unsigned dst, const void* src) {
    asm volatile("cp.async.cg.shared.global [%0], [%1], 16;"
                 :: "r"(dst), "l"(src));
}

#define LDSM_X4(r, addr) \
    asm volatile("ldmatrix.sync.aligned.m8n8.x4.shared.b16 {%0,%1,%2,%3}, [%4];" \
        : "=r"((r)[0]), "=r"((r)[1]), "=r"((r)[2]), "=r"((r)[3]) : "r"(addr))
#define LDSM_X4T(r, addr) \
    asm volatile("ldmatrix.sync.aligned.m8n8.x4.trans.shared.b16 {%0,%1,%2,%3}, [%4];" \
        : "=r"((r)[0]), "=r"((r)[1]), "=r"((r)[2]), "=r"((r)[3]) : "r"(addr))
#define MMA_F16(d, a, b0, b1) \
    asm volatile("mma.sync.aligned.m16n8k16.row.col.f32.f16.f16.f32 " \
        "{%0,%1,%2,%3}, {%4,%5,%6,%7}, {%8,%9}, {%0,%1,%2,%3};" \
        : "+f"((d)[0]), "+f"((d)[1]), "+f"((d)[2]), "+f"((d)[3]) \
        : "r"((a)[0]), "r"((a)[1]), "r"((a)[2]), "r"((a)[3]), "r"(b0), "r"(b1))

// ---------------- prep: xg_table[v][g][h] = emb[v] @ W[g] + bW[g] --------
__global__ void xg_kernel(const float* __restrict__ emb,
                          const float* __restrict__ W,
                          const float* __restrict__ bW) {
    __shared__ float se[E_];
    int v = blockIdx.x;
    int h = threadIdx.x;                     // 256 threads
    se[h] = emb[v * E_ + h];
    __syncthreads();
    float a0 = bW[0 * H_ + h];
    float a1 = bW[1 * H_ + h];
    float a2 = bW[2 * H_ + h];
    float a3 = bW[3 * H_ + h];
    for (int e = 0; e < E_; e++) {
        float x = se[e];
        a0 += x * W[(0 * E_ + e) * H_ + h];
        a1 += x * W[(1 * E_ + e) * H_ + h];
        a2 += x * W[(2 * E_ + e) * H_ + h];
        a3 += x * W[(3 * E_ + e) * H_ + h];
    }
    g_xg[(v * 4 + 0) * H_ + h] = a0;
    g_xg[(v * 4 + 1) * H_ + h] = a1;
    g_xg[(v * 4 + 2) * H_ + h] = a2;
    g_xg[(v * 4 + 3) * H_ + h] = a3;
}

// ---------------- prep: U -> fp16, permuted layout ------------------------
// g_Uf[k][kb*160 + g*32 + c] = U[g][k>=256][k&255][kb*32 + c]
__global__ void ucat_kernel(const float* __restrict__ U) {
    int idx = blockIdx.x * blockDim.x + threadIdx.x;
    if (idx < 512 * 1280) {
        int k = idx / 1280;
        int np = idx - k * 1280;
        int kb = np / 160;
        int rem = np - kb * 160;
        int g = rem >> 5;
        int c = rem & 31;
        int s = k >> 8;
        int hh = k & 255;
        g_Uf[idx] = __float2half(U[(((g * 2 + s) * H_) + hh) * H_ + kb * 32 + c]);
    }
}

// ---------------- leaf level (lev 10): children are zero ------------------
__global__ void leaf_kernel(const int* __restrict__ ids) {
    int idx = blockIdx.x * 256 + threadIdx.x;   // 64*1024*256 total
    int r = idx >> 8;
    int k = idx & 255;
    int b = r >> 10;
    int j = r & 1023;
    int id = ids[b * TOTAL_ + 1022 + j];
    const float* xg = &g_xg[id * 4 * H_];
    float ig = sigmoid_(xg[1 * H_ + k]);
    float og = sigmoid_(xg[2 * H_ + k]);
    float ug = tanh_(xg[3 * H_ + k]);
    float cv = ig * ug;
    float hv = og * tanh_(cv);
    g_c[0][idx] = cv;
    g_hh[0][idx] = __float2half(hv);
}

// ---------------- inner level: tensor-core [hl|hr]@Ucat + fused gates -----
// CTA tile: 128 rows x 32 k-cols (x 5 gates = 160 N). K=512 in 32-chunks.
// fp16 single product (A and B both fp16).
// 2-stage cp.async double-buffered pipeline hides L2 latency.
// 8 warps; warp w handles rows w*16..w*16+15, all 160 N cols.
#define BM_ 128
#define TK_ 32
#define APAD_ 40    // A smem row stride (fp16)
#define BPAD_ 168   // B smem row stride (fp16)
#define A_EL_ (BM_ * APAD_)     // 5120 halves per stage
#define B_EL_ (TK_ * BPAD_)     // 5376 halves per stage
__global__ __launch_bounds__(256, 2) void inner_kernel(
        const int* __restrict__ ids, int off, int log2n,
        int in_buf, int out_buf) {
    extern __shared__ __align__(16) __half sm[];
    __half* AhS = sm;                     // [2][BM_][APAD_]
    __half* BsS = sm + 2 * A_EL_;         // [2][TK_][BPAD_]

    const __half* __restrict__ hhin = g_hh[in_buf];
    const float* __restrict__ cin = g_c[in_buf];
    __half* __restrict__ hhout = g_hh[out_buf];
    float* __restrict__ cout = g_c[out_buf];

    int tid = threadIdx.x;
    int w = tid >> 5;
    int t = tid & 31;
    int rowBase = blockIdx.x * BM_;
    int kb = blockIdx.y;            // H col block: k0 = kb*32
    int k0 = kb * 32;

    float acc[20][4];               // [n8-tile][frag]; nt = g*4 + q
    #pragma unroll
    for (int i = 0; i < 20; i++)
        #pragma unroll
        for (int j = 0; j < 4; j++) acc[i][j] = 0.0f;

    int lrow = (t & 7) + ((t >> 3) & 1) * 8;   // row within 16
    int lcol = (t >> 4) * 8;                   // col-half within 16

    auto load_chunk = [&](int kc, int s) {
        int side = kc >> 8;                    // left / right child
        int col0 = kc & 255;                   // col base within child row
        unsigned ah = s2u_(AhS + s * A_EL_);
        unsigned bb = s2u_(BsS + s * B_EL_);
        // A: 512 16B-slots
        #pragma unroll
        for (int it = 0; it < 2; it++) {
            int idx = tid + it * 256;          // 0..511
            int row = idx >> 2;
            int q = idx & 3;
            int child = 2 * (rowBase + row) + side;
            long gs = (long)child * H_ + col0 + q * 8;
            cpa16_(ah + (unsigned)(row * APAD_ + q * 8) * 2, hhin + gs);
        }
        // B: 640 16B-slots
        for (int idx = tid; idx < 640; idx += 256) {
            int kk = idx / 20;
            int seg = idx - kk * 20;
            long gs = (long)(kc + kk) * 1280 + kb * 160 + seg * 8;
            cpa16_(bb + (unsigned)(kk * BPAD_ + seg * 8) * 2, g_Uf + gs);
        }
    };

    load_chunk(0, 0);
    asm volatile("cp.async.commit_group;");

    for (int c = 0; c < 16; c++) {
        int s = c & 1;
        if (c + 1 < 16) {
            load_chunk((c + 1) * TK_, 1 - s);
            asm volatile("cp.async.commit_group;");
            asm volatile("cp.async.wait_group 1;");
        } else {
            asm volatile("cp.async.wait_group 0;");
        }
        __syncthreads();

        const __half* Ahp = AhS + s * A_EL_;
        const __half* Bsp = BsS + s * B_EL_;
        #pragma unroll
        for (int ks = 0; ks < 2; ks++) {
            unsigned ah[4];
            LDSM_X4(ah, s2u_(Ahp + (w * 16 + lrow) * APAD_ + ks * 16 + lcol));
            #pragma unroll
            for (int ntp = 0; ntp < 10; ntp++) {
                unsigned bf[4];
                LDSM_X4T(bf, s2u_(Bsp + (ks * 16 + lrow) * BPAD_ + ntp * 16 + lcol));
                MMA_F16(acc[2 * ntp], ah, bf[0], bf[1]);
                MMA_F16(acc[2 * ntp + 1], ah, bf[2], bf[3]);
            }
        }
        __syncthreads();
    }

    // ---- epilogue: xg gather + gates + c/h update ----
    // C frag: thread t holds rows w*16 + t/4 (+8), cols (t%4)*2 (+1) of each
    // n8-tile; gates are 4 n8-tiles apart -> all 5 gates local per (row,col).
    int n = 1 << log2n;
    #pragma unroll
    for (int h2 = 0; h2 < 2; h2++) {
        int r = rowBase + w * 16 + (t >> 2) + h2 * 8;
        int b = r >> log2n;
        int j = r & (n - 1);
        int id = ids[b * TOTAL_ + off + j];
        const float* xg = &g_xg[id * 4 * H_];
        #pragma unroll
        for (int q = 0; q < 4; q++) {
            int k = k0 + q * 8 + (t & 3) * 2;
            float2 x0 = *reinterpret_cast<const float2*>(&xg[0 * H_ + k]);
            float2 x1 = *reinterpret_cast<const float2*>(&xg[1 * H_ + k]);
            float2 x2 = *reinterpret_cast<const float2*>(&xg[2 * H_ + k]);
            float2 x3 = *reinterpret_cast<const float2*>(&xg[3 * H_ + k]);
            float2 cl = *reinterpret_cast<const float2*>(&cin[(2 * r) * H_ + k]);
            float2 cr = *reinterpret_cast<const float2*>(&cin[(2 * r + 1) * H_ + k]);
            float2 cv2, hv2;
            __half2 hh2;
            #pragma unroll
            for (int cc = 0; cc < 2; cc++) {
                int i = h2 * 2 + cc;
                float xg0 = cc ? x0.y : x0.x;
                float xg1 = cc ? x1.y : x1.x;
                float xg2 = cc ? x2.y : x2.x;
                float xg3 = cc ? x3.y : x3.x;
                float clv = cc ? cl.y : cl.x;
                float crv = cc ? cr.y : cr.x;
                // gate_map = [0,0,1,2,3]
                float fl = sigmoid_(acc[0 * 4 + q][i] + xg0);
                float fr = sigmoid_(acc[1 * 4 + q][i] + xg0);
                float ig = sigmoid_(acc[2 * 4 + q][i] + xg1);
                float og = sigmoid_(acc[3 * 4 + q][i] + xg2);
                float ug = tanh_(acc[4 * 4 + q][i] + xg3);
                float cv = ig * ug + fl * clv + fr * crv;
                float hv = og * tanh_(cv);
                if (cc) { cv2.y = cv; hv2.y = hv; hh2.y = __float2half(hv); }
                else    { cv2.x = cv; hv2.x = hv; hh2.x = __float2half(hv); }
            }
            *reinterpret_cast<float2*>(&cout[r * H_ + k]) = cv2;
            *reinterpret_cast<__half2*>(&hhout[r * H_ + k]) = hh2;
            if (log2n == 1)     // root level: keep fp32 h for the output
                *reinterpret_cast<float2*>(&g_hf[r * H_ + k]) = hv2;
        }
    }
}

// ---------------- final: root_hidden + scores -----------------------------
// out layout: [0 .. B*3) scores, [B*3 .. B*3 + B*512) root_hidden
__global__ void final_kernel(const float* __restrict__ Ws,
                             const float* __restrict__ bs,
                             float* __restrict__ out) {
    __shared__ float red[512];
    int b = blockIdx.x;
    int t = threadIdx.x;                 // 512 threads
    float rh = g_hf[(b * 2 + (t >> 8)) * H_ + (t & 255)];
    out[B_ * 3 + b * 512 + t] = rh;
    #pragma unroll
    for (int s = 0; s < 3; s++) {
        red[t] = rh * Ws[t * 3 + s];
        __syncthreads();
        for (int st = 256; st > 0; st >>= 1) {
            if (t < st) red[t] += red[t + st];
            __syncthreads();
        }
        if (t == 0) out[b * 3 + s] = red[0] + bs[s];
        __syncthreads();
    }
}

// ---------------- launcher ------------------------------------------------
extern "C" void kernel_launch(void* const* d_in, const int* in_sizes, int n_in,
                              void* d_out, int out_size) {
    const int*   ids = (const int*)d_in[0];
    const float* emb = (const float*)d_in[1];
    const float* W   = (const float*)d_in[2];
    const float* bW  = (const float*)d_in[3];
    const float* U   = (const float*)d_in[4];
    const float* Ws  = (const float*)d_in[5];
    const float* bs  = (const float*)d_in[6];
    float* out = (float*)d_out;

    int smemBytes = (2 * A_EL_ + 2 * B_EL_) * 2;   // 41984 B
    static int attrSet = 0;
    if (!attrSet) {
        cudaFuncSetAttribute(inner_kernel,
            cudaFuncAttributeMaxDynamicSharedMemorySize, smemBytes);
        attrSet = 1;
    }

    xg_kernel<<<V_, 256>>>(emb, W, bW);
    ucat_kernel<<<(512 * 1280 + 255) / 256, 256>>>(U);
    leaf_kernel<<<(B_ * 1024 * H_) / 256, 256>>>(ids);

    int cur = 0;
    for (int lev = 9; lev >= 1; lev--) {
        int n = 1 << lev;
        int M = B_ * n;
        dim3 grid(M / BM_, 8);
        inner_kernel<<<grid, 256, smemBytes>>>(ids, n - 2, lev, cur, 1 - cur);
        cur = 1 - cur;
    }
    final_kernel<<<B_, 512>>>(Ws, bs, out);
}